// round 12
// baseline (speedup 1.0000x reference)
#include <cuda_runtime.h>

#define NN 20480
#define PP (2*NN)           // 40960 points
#define SS (PP*16)          // 655360 samples

#define OBN1 0
#define OBN2 64
#define OBN3 128
#define OBN4 192
#define OBN5 256
#define OBN6 384
#define OBN7 640

// ---- scratch layout inside d_out (floats). NO device globals anywhere. ----
#define F_BUFA  0u            // y1 then y3: PP*64 = 2621440
#define F_SML   5201920u      // tables, tail of Q1 (overwritten only by final kernel)
#define F_WT1   (F_SML)
#define F_WT2   (F_SML+16384u)
#define F_ACC   (F_SML+32768u)   // 2048
#define F_SCALE (F_SML+34816u)   // 1024
#define F_SHIFT (F_SML+35840u)   // 1024
#define F_FLAG  (F_SML+36864u)
#define F_AGG   5242880u      // agg/y5 rows: row p at F_AGG + p*128 (PP*128)

#define NBLK_FINAL 512
#define PTS_FINAL  80

// ---------- f32x2 packed-FMA helpers (SASS FFMA2; used ONLY in att_gemm) ----------
__device__ __forceinline__ void fma2(unsigned long long& d, unsigned long long a,
                                     unsigned long long b) {
    asm("fma.rn.f32x2 %0, %1, %2, %0;" : "+l"(d) : "l"(a), "l"(b));
}
__device__ __forceinline__ float fold2(unsigned long long v) {
    float a, b;
    asm("mov.b64 {%0,%1}, %2;" : "=f"(a), "=f"(b) : "l"(v));
    return a + b;
}

// ---------- helpers ----------
__device__ __forceinline__ int ldidx(const int* __restrict__ idx, size_t s, int u64) {
    return u64 ? __ldg(&idx[2*s]) : __ldg(&idx[s]);
}

__device__ __forceinline__ void build_e(const float* __restrict__ xyz,
                                        const int* __restrict__ idx, size_t s, int u64,
                                        float* e) {
    int p = (int)(s >> 4);
    int b = p / NN, n = p % NN;
    int ni = ldidx(idx, s, u64);
    const float* cx = &xyz[((size_t)b*NN + n)*3];
    const float* nx = &xyz[((size_t)b*NN + ni)*3];
    float c0=__ldg(cx), c1=__ldg(cx+1), c2=__ldg(cx+2);
    float n0=__ldg(nx), n1=__ldg(nx+1), n2=__ldg(nx+2);
    float r0=c0-n0, r1=c1-n1, r2=c2-n2;
    e[0]=sqrtf(r0*r0+r1*r1+r2*r2);
    e[1]=r0; e[2]=r1; e[3]=r2; e[4]=c0; e[5]=c1; e[6]=c2; e[7]=n0; e[8]=n1; e[9]=n2;
}

template<int CIN>
__device__ __forceinline__ float4 dot4(const float* Wsh, int og, const float* x) {
    float4 a = make_float4(0.f,0.f,0.f,0.f);
    const float* w0 = Wsh + (4*og+0)*CIN;
    const float* w1 = Wsh + (4*og+1)*CIN;
    const float* w2 = Wsh + (4*og+2)*CIN;
    const float* w3 = Wsh + (4*og+3)*CIN;
#pragma unroll
    for (int cq = 0; cq < CIN/4; cq++) {
        float4 p0 = *(const float4*)(w0+4*cq);
        float4 p1 = *(const float4*)(w1+4*cq);
        float4 p2 = *(const float4*)(w2+4*cq);
        float4 p3 = *(const float4*)(w3+4*cq);
        float x0=x[4*cq], x1=x[4*cq+1], x2=x[4*cq+2], x3=x[4*cq+3];
        a.x += p0.x*x0+p0.y*x1+p0.z*x2+p0.w*x3;
        a.y += p1.x*x0+p1.y*x1+p1.z*x2+p1.w*x3;
        a.z += p2.x*x0+p2.y*x1+p2.z*x2+p2.w*x3;
        a.w += p3.x*x0+p3.y*x1+p3.z*x2+p3.w*x3;
    }
    return a;
}

// ---------- kernels ----------
__global__ void k_init(const int* __restrict__ idx, float* __restrict__ f) {
    __shared__ int hi[256];
    int t = threadIdx.x;
    long long v = __ldg(&((const long long*)idx)[t]);
    hi[t] = (int)((unsigned long long)v >> 32);
    __syncthreads();
    if (t == 0) {
        int o = 0;
        for (int j = 0; j < 256; j++) o |= hi[j];
        *(int*)&f[F_FLAG] = (o == 0) ? 1 : 0;
    }
    for (int i = t; i < 2048; i += 256) f[F_ACC + i] = 0.f;
}

// W transposed into PAIRED layout: dst[(c/2)*256 + o*2 + (c&1)] = W[o][c]
__global__ void k_transpose(const float* __restrict__ W1, const float* __restrict__ W2,
                            float* __restrict__ f) {
    const float* src = blockIdx.x ? W2 : W1;
    float* dst = f + (blockIdx.x ? F_WT2 : F_WT1);
    for (int i = threadIdx.x; i < 16384; i += 256) {
        int o = i >> 7, c = i & 127;
        dst[(c>>1)*256 + o*2 + (c&1)] = __ldg(&src[i]);
    }
}

// mlp1 (64->64) raw -> bufA. grid 160x256.
__global__ __launch_bounds__(256) void k_mlp1(const float* __restrict__ feat,
                                              const float* __restrict__ W1,
                                              float* __restrict__ f) {
    __shared__ float Wsh[4096];
    int t = threadIdx.x;
    int p = blockIdx.x*256 + t;
    int b = p / NN, n = p % NN;
    float x[64];
#pragma unroll
    for (int c = 0; c < 64; c++) x[c] = __ldg(&feat[((size_t)(b*64+c))*NN + n]);
    for (int i = t; i < 4096; i += 256) Wsh[i] = __ldg(&W1[i]);
    __syncthreads();
#pragma unroll 2
    for (int og = 0; og < 16; og++)
        *(float4*)&f[F_BUFA + (size_t)p*64 + 4*og] = dot4<64>(Wsh, og, x);
}

// shortcut conv (64->256) stats only. dyn smem 74752B. (R9 scalar version)
__global__ __launch_bounds__(256) void k_scstats(const float* __restrict__ feat,
                                                 const float* __restrict__ Wsc,
                                                 float* __restrict__ f) {
    extern __shared__ float sh[];
    float* Wsh = sh;            // [256][65]
    float* xf  = sh + 16640;    // [64][32]
    int t = threadIdx.x;
    for (int i = t; i < 16384; i += 256) Wsh[(i>>6)*65 + (i&63)] = __ldg(&Wsc[i]);
    float sum = 0.f, sq = 0.f;
    for (int tile = blockIdx.x; tile < PP/32; tile += gridDim.x) {
        __syncthreads();
        int pbase = tile*32, b = pbase/NN, nb = pbase%NN;
        for (int i = t; i < 2048; i += 256) {
            int cin = i >> 5, ii = i & 31;
            xf[i] = __ldg(&feat[((size_t)(b*64+cin))*NN + nb + ii]);
        }
        __syncthreads();
        float a[32];
#pragma unroll
        for (int u = 0; u < 32; u++) a[u] = 0.f;
#pragma unroll 4
        for (int j = 0; j < 64; j++) {
            float w = Wsh[t*65 + j];
            const float4* xr = (const float4*)&xf[j*32];
#pragma unroll
            for (int i4 = 0; i4 < 8; i4++) {
                float4 xv = xr[i4];
                a[i4*4+0] += w*xv.x; a[i4*4+1] += w*xv.y;
                a[i4*4+2] += w*xv.z; a[i4*4+3] += w*xv.w;
            }
        }
#pragma unroll
        for (int u = 0; u < 32; u++) { sum += a[u]; sq += a[u]*a[u]; }
    }
    atomicAdd(&f[F_ACC + OBN7 + t], sum);
    atomicAdd(&f[F_ACC + 1024 + OBN7 + t], sq);
}

// bb1 stats only: recompute posenc per 128-sample tile.
__global__ __launch_bounds__(256) void k_bn2stats(const float* __restrict__ xyz,
                                                  const int* __restrict__ idx,
                                                  const float* __restrict__ Wbb1,
                                                  float* __restrict__ f) {
    __shared__ float Wsh[704], esh[1408], red[2048];
    int t = threadIdx.x;
    int u64 = __ldg((const int*)&f[F_FLAG]);
    for (int i = t; i < 640; i += 256) Wsh[(i/10)*11 + (i%10)] = __ldg(&Wbb1[i]);
    float acc[8];
#pragma unroll
    for (int i = 0; i < 8; i++) acc[i] = 0.f;
    int q = t & 15, so = t >> 4;
    for (int tile = blockIdx.x; tile < SS/128; tile += gridDim.x) {
        __syncthreads();
        if (t < 128) build_e(xyz, idx, (size_t)tile*128 + t, u64, &esh[t*11]);
        __syncthreads();
        float a4[32];
#pragma unroll
        for (int u = 0; u < 32; u++) a4[u] = 0.f;
#pragma unroll
        for (int c = 0; c < 10; c++) {
            float w0 = Wsh[(4*q+0)*11+c], w1 = Wsh[(4*q+1)*11+c];
            float w2 = Wsh[(4*q+2)*11+c], w3 = Wsh[(4*q+3)*11+c];
#pragma unroll
            for (int j = 0; j < 8; j++) {
                float ev = esh[(j*16+so)*11+c];
                a4[j*4+0] += w0*ev; a4[j*4+1] += w1*ev;
                a4[j*4+2] += w2*ev; a4[j*4+3] += w3*ev;
            }
        }
#pragma unroll
        for (int j = 0; j < 8; j++)
#pragma unroll
            for (int cc = 0; cc < 4; cc++) {
                float v = a4[j*4+cc];
                acc[cc] += v; acc[4+cc] += v*v;
            }
    }
    __syncthreads();
#pragma unroll
    for (int i = 0; i < 8; i++) red[t*8+i] = acc[i];
    __syncthreads();
    if (t < 128) {
        int qq = t & 15, ii = t >> 4;
        float s = 0.f;
#pragma unroll
        for (int g = 0; g < 16; g++) s += red[(g*16+qq)*8+ii];
        int ch = 4*qq + (ii & 3);
        if (ii < 4) atomicAdd(&f[F_ACC + OBN2 + ch], s);
        else        atomicAdd(&f[F_ACC + 1024 + OBN2 + ch], s);
    }
}

// bb2 stats only: recompute y2 tile -> bn2relu -> Wbb2. dyn smem 57856B.
__global__ __launch_bounds__(256) void k_y4stats(const float* __restrict__ xyz,
                                                 const int* __restrict__ idx,
                                                 const float* __restrict__ Wbb1,
                                                 const float* __restrict__ Wbb2,
                                                 float* __restrict__ f) {
    extern __shared__ float sh[];
    float* W1s  = sh;
    float* W2s  = sh + 704;
    float* y2sh = sh + 4864;
    float* esh  = sh + 13056;
    int t = threadIdx.x;
    int u64 = __ldg((const int*)&f[F_FLAG]);
    for (int i = t; i < 640; i += 256) W1s[(i/10)*11 + (i%10)] = __ldg(&Wbb1[i]);
    for (int i = t; i < 4096; i += 256) W2s[(i>>6)*65 + (i&63)] = __ldg(&Wbb2[i]);
    float acc[8];
#pragma unroll
    for (int i = 0; i < 8; i++) acc[i] = 0.f;
    int q = t & 15, so = t >> 4;
    for (int tile = blockIdx.x; tile < SS/128; tile += gridDim.x) {
        __syncthreads();
        if (t < 128) build_e(xyz, idx, (size_t)tile*128 + t, u64, &esh[t*11]);
        __syncthreads();
        {
            float a4[32];
#pragma unroll
            for (int u = 0; u < 32; u++) a4[u] = 0.f;
#pragma unroll
            for (int c = 0; c < 10; c++) {
                float w0 = W1s[(4*q+0)*11+c], w1 = W1s[(4*q+1)*11+c];
                float w2 = W1s[(4*q+2)*11+c], w3 = W1s[(4*q+3)*11+c];
#pragma unroll
                for (int j = 0; j < 8; j++) {
                    float ev = esh[(j*16+so)*11+c];
                    a4[j*4+0] += w0*ev; a4[j*4+1] += w1*ev;
                    a4[j*4+2] += w2*ev; a4[j*4+3] += w3*ev;
                }
            }
#pragma unroll
            for (int j = 0; j < 8; j++)
#pragma unroll
                for (int cc = 0; cc < 4; cc++) {
                    int ch = OBN2 + 4*q + cc;
                    y2sh[(j*16+so)*64 + 4*q + cc] =
                        fmaxf(a4[j*4+cc]*f[F_SCALE+ch]+f[F_SHIFT+ch], 0.f);
                }
        }
        __syncthreads();
        {
            float a4[32];
#pragma unroll
            for (int u = 0; u < 32; u++) a4[u] = 0.f;
#pragma unroll 4
            for (int c = 0; c < 64; c++) {
                float w0 = W2s[(4*q+0)*65+c], w1 = W2s[(4*q+1)*65+c];
                float w2 = W2s[(4*q+2)*65+c], w3 = W2s[(4*q+3)*65+c];
#pragma unroll
                for (int j = 0; j < 8; j++) {
                    float yv = y2sh[(j*16+so)*64+c];
                    a4[j*4+0] += w0*yv; a4[j*4+1] += w1*yv;
                    a4[j*4+2] += w2*yv; a4[j*4+3] += w3*yv;
                }
            }
#pragma unroll
            for (int j = 0; j < 8; j++)
#pragma unroll
                for (int cc = 0; cc < 4; cc++) {
                    float v = a4[j*4+cc];
                    acc[cc] += v; acc[4+cc] += v*v;
                }
        }
    }
    __syncthreads();
#pragma unroll
    for (int i = 0; i < 8; i++) y2sh[t*8+i] = acc[i];
    __syncthreads();
    if (t < 128) {
        int qq = t & 15, ii = t >> 4;
        float s = 0.f;
#pragma unroll
        for (int g = 0; g < 16; g++) s += y2sh[(g*16+qq)*8+ii];
        int ch = 4*qq + (ii & 3);
        if (ii < 4) atomicAdd(&f[F_ACC + OBN4 + ch], s);
        else        atomicAdd(&f[F_ACC + 1024 + OBN4 + ch], s);
    }
}

// generic column stats
__global__ void k_stats(const float* __restrict__ buf, float* __restrict__ f,
                        int nrows, int C, int off) {
    __shared__ float rs[256], rq[256];
    int t = threadIdx.x;
    int c = t & 31, r = t >> 5;
    int col = blockIdx.x*32 + c;
    float s = 0.f, q = 0.f;
    int stride = gridDim.y*8;
    for (int p = blockIdx.y*8 + r; p < nrows; p += stride) {
        float v = __ldg(&buf[(size_t)p*C + col]);
        s += v; q += v*v;
    }
    rs[t] = s; rq[t] = q;
    __syncthreads();
    if (t < 32) {
        float ss = 0.f, qq = 0.f;
#pragma unroll
        for (int j = 0; j < 8; j++) { ss += rs[j*32+t]; qq += rq[j*32+t]; }
        atomicAdd(&f[F_ACC + off + blockIdx.x*32 + t], ss);
        atomicAdd(&f[F_ACC + 1024 + off + blockIdx.x*32 + t], qq);
    }
}

__global__ void k_finalize(float* __restrict__ f, int off, int C, float invn,
                           const float* __restrict__ gamma, const float* __restrict__ beta) {
    int c = threadIdx.x;
    if (c < C) {
        float mean = f[F_ACC+off+c]*invn;
        float var  = f[F_ACC+1024+off+c]*invn - mean*mean;
        float sc   = __ldg(&gamma[c]) * rsqrtf(var + 1e-5f);
        f[F_SCALE+off+c] = sc;
        f[F_SHIFT+off+c] = __ldg(&beta[c]) - mean*sc;
    }
}

// GEMM+softmax+agg epilogue: f32x2 with paired-channel partial sums.
// WT in paired layout [c/2][o][2].
__device__ __forceinline__ void att_gemm(const float* __restrict__ fsh,
                                         const float* __restrict__ WT,
                                         float* __restrict__ f,
                                         int pair, int half, int o) {
    const float* ff = fsh + half*2048;
    unsigned long long acc2[16];
#pragma unroll
    for (int k = 0; k < 16; k++) acc2[k] = 0ull;
#pragma unroll 2
    for (int c0 = 0; c0 < 128; c0 += 4) {
        unsigned long long w01 = __ldg((const unsigned long long*)&WT[(c0>>1)*256 + 2*o]);
        unsigned long long w23 = __ldg((const unsigned long long*)&WT[(c0>>1)*256 + 256 + 2*o]);
#pragma unroll
        for (int k = 0; k < 16; k++) {
            ulonglong2 fv = *(const ulonglong2*)&ff[k*128 + c0];
            fma2(acc2[k], w01, fv.x);
            fma2(acc2[k], w23, fv.y);
        }
    }
    float acc[16];
#pragma unroll
    for (int k = 0; k < 16; k++) acc[k] = fold2(acc2[k]);
    float m = acc[0];
#pragma unroll
    for (int k = 1; k < 16; k++) m = fmaxf(m, acc[k]);
    float den = 0.f;
#pragma unroll
    for (int k = 0; k < 16; k++) { acc[k] = __expf(acc[k]-m); den += acc[k]; }
    float a = 0.f;
#pragma unroll
    for (int k = 0; k < 16; k++) a += ff[k*128+o]*acc[k];
    f[F_AGG + ((size_t)pair*2 + half)*128 + o] = a / den;
}

// prefetch next pair: gather rows (2x float4) + e-inputs (t<32: 6 floats)
__device__ __forceinline__ void att_prefetch(const float* __restrict__ f,
                                             const float* __restrict__ xyz,
                                             const int* __restrict__ idx,
                                             int pair, int t, int u64, int q4,
                                             float4* gv, float* er) {
    if (pair >= PP/2) return;
    int k = t >> 4;
#pragma unroll
    for (int ph = 0; ph < 2; ph++) {
        int p = pair*2 + ph;
        size_t s = (size_t)p*16 + k;
        int ni = ldidx(idx, s, u64);
        size_t pn = (size_t)(p / NN) * NN + ni;
        gv[ph] = __ldg((const float4*)&f[F_BUFA + pn*64 + q4]);
    }
    if (t < 32) {
        size_t se = (size_t)pair*32 + t;
        int pe = pair*2 + (t >> 4);
        int be = pe / NN, ne = pe % NN;
        int nie = ldidx(idx, se, u64);
        const float* cx = &xyz[((size_t)be*NN + ne)*3];
        const float* nx = &xyz[((size_t)be*NN + nie)*3];
        er[0]=__ldg(cx);  er[1]=__ldg(cx+1); er[2]=__ldg(cx+2);
        er[3]=__ldg(nx);  er[4]=__ldg(nx+1); er[5]=__ldg(nx+2);
    }
}

__device__ __forceinline__ void commit_e(float* __restrict__ esh, const float* er, int t) {
    if (t < 32) {
        float r0 = er[0]-er[3], r1 = er[1]-er[4], r2 = er[2]-er[5];
        float* e = &esh[t*11];
        e[0] = sqrtf(r0*r0 + r1*r1 + r2*r2);
        e[1]=r0; e[2]=r1; e[3]=r2;
        e[4]=er[0]; e[5]=er[1]; e[6]=er[2]; e[7]=er[3]; e[8]=er[4]; e[9]=er[5];
    }
}

// att-pool 1: pipelined. dyn smem 20608B.
__global__ __launch_bounds__(256) void k_attpool1(float* __restrict__ f,
                                                  const float* __restrict__ xyz,
                                                  const int* __restrict__ idx,
                                                  const float* __restrict__ Wbb1) {
    extern __shared__ float sh[];
    float* fsh = sh;
    float* W1s = sh + 4096;
    float* esh = sh + 4800;
    const float* WT = f + F_WT1;
    int t = threadIdx.x;
    int u64 = __ldg((const int*)&f[F_FLAG]);
    for (int i = t; i < 640; i += 256) W1s[(i/10)*11 + (i%10)] = __ldg(&Wbb1[i]);
    int half = t >> 7, o = t & 127;
    int kq = t >> 4, q4 = (t & 15)*4, qq = t & 15;
    float s1[4], h1[4], s2[4], h2[4];
#pragma unroll
    for (int c = 0; c < 4; c++) {
        s1[c] = __ldg(&f[F_SCALE+OBN1+q4+c]); h1[c] = __ldg(&f[F_SHIFT+OBN1+q4+c]);
        s2[c] = __ldg(&f[F_SCALE+OBN2+q4+c]); h2[c] = __ldg(&f[F_SHIFT+OBN2+q4+c]);
    }
    float4 gv[2]; float er[6];
    int step = gridDim.x;
    att_prefetch(f, xyz, idx, blockIdx.x, t, u64, q4, gv, er);

    for (int pair = blockIdx.x; pair < PP/2; pair += step) {
        commit_e(esh, er, t);
#pragma unroll
        for (int ph = 0; ph < 2; ph++) {
            float4 v = gv[ph];
            v.x = fmaxf(v.x*s1[0]+h1[0],0.f); v.y = fmaxf(v.y*s1[1]+h1[1],0.f);
            v.z = fmaxf(v.z*s1[2]+h1[2],0.f); v.w = fmaxf(v.w*s1[3]+h1[3],0.f);
            *(float4*)&fsh[ph*2048 + kq*128 + q4] = v;
        }
        __syncthreads();
#pragma unroll
        for (int ph = 0; ph < 2; ph++) {
            const float* e = &esh[(ph*16 + kq)*11];
            float a0=0,a1=0,a2=0,a3=0;
#pragma unroll
            for (int c = 0; c < 10; c++) {
                float ev = e[c];
                a0 += W1s[(4*qq+0)*11+c]*ev; a1 += W1s[(4*qq+1)*11+c]*ev;
                a2 += W1s[(4*qq+2)*11+c]*ev; a3 += W1s[(4*qq+3)*11+c]*ev;
            }
            float4 v;
            v.x = fmaxf(a0*s2[0]+h2[0],0.f); v.y = fmaxf(a1*s2[1]+h2[1],0.f);
            v.z = fmaxf(a2*s2[2]+h2[2],0.f); v.w = fmaxf(a3*s2[3]+h2[3],0.f);
            *(float4*)&fsh[ph*2048 + kq*128 + 64 + q4] = v;
        }
        __syncthreads();
        att_prefetch(f, xyz, idx, pair + step, t, u64, q4, gv, er);
        att_gemm(fsh, WT, f, pair, half, o);
        __syncthreads();
    }
}

// att-pool 2: pipelined. dyn smem 45440B.
__global__ __launch_bounds__(256) void k_attpool2(float* __restrict__ f,
                                                  const float* __restrict__ xyz,
                                                  const int* __restrict__ idx,
                                                  const float* __restrict__ Wbb1,
                                                  const float* __restrict__ Wbb2) {
    extern __shared__ float sh[];
    float* fsh = sh;
    float* W1s = sh + 4096;
    float* W2s = sh + 4800;
    float* esh = sh + 8960;
    float* y2t = sh + 9312;
    const float* WT = f + F_WT2;
    int t = threadIdx.x;
    int u64 = __ldg((const int*)&f[F_FLAG]);
    for (int i = t; i < 640; i += 256) W1s[(i/10)*11 + (i%10)] = __ldg(&Wbb1[i]);
    for (int i = t; i < 4096; i += 256) W2s[(i>>6)*65 + (i&63)] = __ldg(&Wbb2[i]);
    int half = t >> 7, o = t & 127;
    int kq = t >> 4, q4 = (t & 15)*4, qq = t & 15;
    float s3[4], h3[4], s2[4], h2[4], s4[4], h4[4];
#pragma unroll
    for (int c = 0; c < 4; c++) {
        s3[c] = __ldg(&f[F_SCALE+OBN3+q4+c]); h3[c] = __ldg(&f[F_SHIFT+OBN3+q4+c]);
        s2[c] = __ldg(&f[F_SCALE+OBN2+q4+c]); h2[c] = __ldg(&f[F_SHIFT+OBN2+q4+c]);
        s4[c] = __ldg(&f[F_SCALE+OBN4+q4+c]); h4[c] = __ldg(&f[F_SHIFT+OBN4+q4+c]);
    }
    float4 gv[2]; float er[6];
    int step = gridDim.x;
    att_prefetch(f, xyz, idx, blockIdx.x, t, u64, q4, gv, er);

    for (int pair = blockIdx.x; pair < PP/2; pair += step) {
        commit_e(esh, er, t);
#pragma unroll
        for (int ph = 0; ph < 2; ph++) {
            float4 v = gv[ph];
            v.x = fmaxf(v.x*s3[0]+h3[0],0.f); v.y = fmaxf(v.y*s3[1]+h3[1],0.f);
            v.z = fmaxf(v.z*s3[2]+h3[2],0.f); v.w = fmaxf(v.w*s3[3]+h3[3],0.f);
            *(float4*)&fsh[ph*2048 + kq*128 + q4] = v;
        }
        __syncthreads();
#pragma unroll
        for (int ph = 0; ph < 2; ph++) {
            int sl = ph*16 + kq;
            const float* e = &esh[sl*11];
            float a0=0,a1=0,a2=0,a3=0;
#pragma unroll
            for (int c = 0; c < 10; c++) {
                float ev = e[c];
                a0 += W1s[(4*qq+0)*11+c]*ev; a1 += W1s[(4*qq+1)*11+c]*ev;
                a2 += W1s[(4*qq+2)*11+c]*ev; a3 += W1s[(4*qq+3)*11+c]*ev;
            }
            float4 v;
            v.x = fmaxf(a0*s2[0]+h2[0],0.f); v.y = fmaxf(a1*s2[1]+h2[1],0.f);
            v.z = fmaxf(a2*s2[2]+h2[2],0.f); v.w = fmaxf(a3*s2[3]+h2[3],0.f);
            *(float4*)&y2t[sl*64 + q4] = v;
        }
        __syncthreads();
#pragma unroll
        for (int ph = 0; ph < 2; ph++) {
            int sl = ph*16 + kq;
            const float* y2 = &y2t[sl*64];
            float a0=0,a1=0,a2=0,a3=0;
#pragma unroll 4
            for (int c = 0; c < 64; c++) {
                float yv = y2[c];
                a0 += W2s[(4*qq+0)*65+c]*yv; a1 += W2s[(4*qq+1)*65+c]*yv;
                a2 += W2s[(4*qq+2)*65+c]*yv; a3 += W2s[(4*qq+3)*65+c]*yv;
            }
            float4 v;
            v.x = fmaxf(a0*s4[0]+h4[0],0.f); v.y = fmaxf(a1*s4[1]+h4[1],0.f);
            v.z = fmaxf(a2*s4[2]+h4[2],0.f); v.w = fmaxf(a3*s4[3]+h4[3],0.f);
            *(float4*)&fsh[ph*2048 + kq*128 + 64 + q4] = v;
        }
        __syncthreads();
        att_prefetch(f, xyz, idx, pair + step, t, u64, q4, gv, er);
        att_gemm(fsh, WT, f, pair, half, o);
        __syncthreads();
    }
}

// tiled rows GEMM (R9 scalar version).
template<int O>
__global__ __launch_bounds__(256) void k_rowsT(const float* __restrict__ X,
                                               float* __restrict__ Y,
                                               const float* __restrict__ W) {
    extern __shared__ float sh[];
    float* Wsh = sh;                  // [O][129]
    float* xsh = sh + O*129;          // [128][36]
    constexpr int NP = (O == 64) ? 8 : 16;
    int t = threadIdx.x;
    int o = t & (O-1), h = t / O;
    for (int i = t; i < O*128; i += 256) Wsh[(i>>7)*129 + (i&127)] = __ldg(&W[i]);
    for (int tile = blockIdx.x; tile < PP/32; tile += gridDim.x) {
        __syncthreads();
        for (int i = t; i < 4096; i += 256) {
            int pt = i >> 7, ch = i & 127;
            xsh[ch*36 + pt] = __ldg(&X[((size_t)tile*32 + pt)*128 + ch]);
        }
        __syncthreads();
        float acc[NP];
#pragma unroll
        for (int i = 0; i < NP; i++) acc[i] = 0.f;
#pragma unroll 4
        for (int j = 0; j < 128; j++) {
            float w = Wsh[o*129 + j];
            const float4* xr = (const float4*)&xsh[j*36 + h*NP];
#pragma unroll
            for (int i4 = 0; i4 < NP/4; i4++) {
                float4 xv = xr[i4];
                acc[i4*4+0] += w*xv.x; acc[i4*4+1] += w*xv.y;
                acc[i4*4+2] += w*xv.z; acc[i4*4+3] += w*xv.w;
            }
        }
#pragma unroll
        for (int i = 0; i < NP; i++)
            Y[((size_t)tile*32 + h*NP + i)*O + o] = acc[i];
    }
}

// mlp2 stats only. dyn smem 84992B. (R9 scalar version)
__global__ __launch_bounds__(256) void k_y6stats(float* __restrict__ f,
                                                 const float* __restrict__ Wm) {
    extern __shared__ float sh[];
    float* Wsh = sh;            // [256][65]
    float* xsh = sh + 16640;    // [128][36]
    int t = threadIdx.x;
    float sum = 0.f, sq = 0.f;
    for (int tile = blockIdx.x; tile < PP/32; tile += gridDim.x) {
        __syncthreads();
        for (int i = t; i < 4096; i += 256) {
            int pt = i >> 7, ch = i & 127;
            float v = __ldg(&f[F_AGG + ((size_t)tile*32 + pt)*128 + ch]);
            xsh[ch*36 + pt] = fmaxf(v*f[F_SCALE+OBN5+ch]+f[F_SHIFT+OBN5+ch], 0.f);
        }
        float a[32];
#pragma unroll
        for (int u = 0; u < 32; u++) a[u] = 0.f;
        for (int chunk = 0; chunk < 2; chunk++) {
            __syncthreads();
            for (int i = t; i < 16384; i += 256)
                Wsh[(i>>6)*65 + (i&63)] = __ldg(&Wm[(i>>6)*128 + chunk*64 + (i&63)]);
            __syncthreads();
#pragma unroll 4
            for (int j = 0; j < 64; j++) {
                float w = Wsh[t*65 + j];
                const float4* xr = (const float4*)&xsh[(chunk*64+j)*36];
#pragma unroll
                for (int i4 = 0; i4 < 8; i4++) {
                    float4 xv = xr[i4];
                    a[i4*4+0] += w*xv.x; a[i4*4+1] += w*xv.y;
                    a[i4*4+2] += w*xv.z; a[i4*4+3] += w*xv.w;
                }
            }
        }
#pragma unroll
        for (int u = 0; u < 32; u++) { sum += a[u]; sq += a[u]*a[u]; }
    }
    atomicAdd(&f[F_ACC + OBN6 + t], sum);
    atomicAdd(&f[F_ACC + 1024 + OBN6 + t], sq);
}

__global__ void k_zeroctr(float* __restrict__ f) {
    ((int*)f)[0] = 0;
    ((int*)f)[1] = 0;
}

// FINAL: grid-barrier kernel. 512 blocks x 80 pts. dyn smem 50176B.
__global__ __launch_bounds__(256, 4) void k_final(float* __restrict__ f,
                                                  const float* __restrict__ feat,
                                                  const float* __restrict__ Wm,
                                                  const float* __restrict__ Wsc) {
    extern __shared__ float sh[];
    float* h     = sh;           // 10240
    float* featT = sh + 10240;   // 1024
    float* sml   = sh + 11264;   // 1280
    int t = threadIdx.x;
    int pb = blockIdx.x * PTS_FINAL;
    int b = (pb >= NN) ? 1 : 0;
    int n0b = pb - b*NN;
    int* ctr  = (int*)&f[0];
    int* ctr2 = (int*)&f[1];

    for (int i = t; i < 1280; i += 256) {
        unsigned src;
        if (i < 128)       src = F_SCALE + OBN5 + i;
        else if (i < 256)  src = F_SHIFT + OBN5 + (i-128);
        else if (i < 512)  src = F_SCALE + OBN6 + (i-256);
        else if (i < 768)  src = F_SHIFT + OBN6 + (i-512);
        else if (i < 1024) src = F_SCALE + OBN7 + (i-768);
        else               src = F_SHIFT + OBN7 + (i-1024);
        sml[i] = __ldg(&f[src]);
    }
    for (int i = t; i < PTS_FINAL*128; i += 256) {
        int pt = i >> 7, ch = i & 127;
        float v = __ldg(&f[F_AGG + ((size_t)(pb + pt))*128 + ch]);
        h[i] = fmaxf(v*__ldg(&f[F_SCALE+OBN5+ch]) + __ldg(&f[F_SHIFT+OBN5+ch]), 0.f);
    }
    __syncthreads();

    if (t == 0) {
        __threadfence();
        atomicAdd(ctr, 1);
        while (atomicAdd(ctr, 0) < NBLK_FINAL) { }
        __threadfence();
    }
    __syncthreads();

    int c = t;
    float s6 = sml[256 + c], h6 = sml[512 + c];
    float s7 = sml[768 + c], h7 = sml[1024 + c];
    float sv0 = 0.f, sv1 = 0.f;
    bool owner = (pb == 0) && (c == 0);

    for (int tt = 0; tt < PTS_FINAL/16; tt++) {
        __syncthreads();
        int n0 = n0b + tt*16;
        for (int i = t; i < 1024; i += 256) {
            int cin = i >> 4, ii = i & 15;
            featT[cin*16 + ii] = __ldg(&feat[((size_t)(b*64+cin))*NN + n0 + ii]);
        }
        __syncthreads();

        float acc[16];
#pragma unroll
        for (int i = 0; i < 16; i++) acc[i] = 0.f;
        const float4* wrow = (const float4*)(Wm + (size_t)c*128);
        const float* hb = h + (tt*16)*128;
#pragma unroll 4
        for (int kk = 0; kk < 32; kk++) {
            float4 w = __ldg(&wrow[kk]);
#pragma unroll
            for (int i = 0; i < 16; i++) {
                float4 hv = *(const float4*)&hb[i*128 + kk*4];
                acc[i] += w.x*hv.x + w.y*hv.y + w.z*hv.z + w.w*hv.w;
            }
        }
#pragma unroll
        for (int i = 0; i < 16; i++) acc[i] = acc[i]*s6 + h6 + h7;

        const float4* srow = (const float4*)(Wsc + (size_t)c*64);
#pragma unroll 4
        for (int j4 = 0; j4 < 16; j4++) {
            float4 w = __ldg(&srow[j4]);
            float wx = w.x*s7, wy = w.y*s7, wz = w.z*s7, ww = w.w*s7;
            const float* f0 = &featT[(j4*4+0)*16];
            const float* f1 = &featT[(j4*4+1)*16];
            const float* f2 = &featT[(j4*4+2)*16];
            const float* f3 = &featT[(j4*4+3)*16];
#pragma unroll
            for (int i = 0; i < 16; i++)
                acc[i] += wx*f0[i] + wy*f1[i] + wz*f2[i] + ww*f3[i];
        }
        size_t obase = ((size_t)(b*256 + c))*NN + n0;
#pragma unroll
        for (int i = 0; i < 16; i++) {
            float v = acc[i];
            v = (v > 0.f) ? v : 0.2f*v;
            if (owner && tt == 0 && i < 2) { if (i == 0) sv0 = v; else sv1 = v; }
            else f[obase + i] = v;
        }
    }

    __syncthreads();
    if (t == 0) {
        __threadfence();
        atomicAdd(ctr2, 1);
        if (pb == 0) {
            while (atomicAdd(ctr2, 0) < NBLK_FINAL) { }
            f[0] = sv0;
            f[1] = sv1;
        }
    }
}

// ---------- launch ----------
extern "C" void kernel_launch(void* const* d_in, const int* in_sizes, int n_in,
                              void* d_out, int out_size) {
    const float* feature = (const float*)d_in[0];
    const float* xyz     = (const float*)d_in[1];
    const int*   nidx    = (const int*)  d_in[2];
    const float* W_mlp1  = (const float*)d_in[3];
    const float* g_mlp1  = (const float*)d_in[4];
    const float* b_mlp1  = (const float*)d_in[5];
    const float* W_bb1   = (const float*)d_in[6];
    const float* g_bb1   = (const float*)d_in[7];
    const float* b_bb1   = (const float*)d_in[8];
    const float* W_a1fc  = (const float*)d_in[9];
    const float* W_a1m   = (const float*)d_in[10];
    const float* g_att1  = (const float*)d_in[11];
    const float* b_att1  = (const float*)d_in[12];
    const float* W_bb2   = (const float*)d_in[13];
    const float* g_bb2   = (const float*)d_in[14];
    const float* b_bb2   = (const float*)d_in[15];
    const float* W_a2fc  = (const float*)d_in[16];
    const float* W_a2m   = (const float*)d_in[17];
    const float* g_att2  = (const float*)d_in[18];
    const float* b_att2  = (const float*)d_in[19];
    const float* W_mlp2  = (const float*)d_in[20];
    const float* g_mlp2  = (const float*)d_in[21];
    const float* b_mlp2  = (const float*)d_in[22];
    const float* W_sc    = (const float*)d_in[23];
    const float* g_sc    = (const float*)d_in[24];
    const float* b_sc    = (const float*)d_in[25];
    float* f = (float*)d_out;

    cudaFuncSetAttribute(k_scstats,   cudaFuncAttributeMaxDynamicSharedMemorySize, 74752);
    cudaFuncSetAttribute(k_y4stats,   cudaFuncAttributeMaxDynamicSharedMemorySize, 57856);
    cudaFuncSetAttribute(k_attpool1,  cudaFuncAttributeMaxDynamicSharedMemorySize, 20608);
    cudaFuncSetAttribute(k_attpool2,  cudaFuncAttributeMaxDynamicSharedMemorySize, 45440);
    cudaFuncSetAttribute(k_y6stats,   cudaFuncAttributeMaxDynamicSharedMemorySize, 84992);
    cudaFuncSetAttribute(k_rowsT<64>, cudaFuncAttributeMaxDynamicSharedMemorySize, 51456);
    cudaFuncSetAttribute(k_rowsT<128>,cudaFuncAttributeMaxDynamicSharedMemorySize, 84480);
    cudaFuncSetAttribute(k_final,     cudaFuncAttributeMaxDynamicSharedMemorySize, 50176);

    const float iPP = 1.f/(float)PP, iSS = 1.f/(float)SS;

    k_init<<<1,256>>>(nidx, f);
    k_transpose<<<2,256>>>(W_a1fc, W_a2fc, f);
    k_mlp1<<<PP/256,256>>>(feature, W_mlp1, f);
    k_scstats<<<320,256,74752>>>(feature, W_sc, f);
    k_bn2stats<<<1184,256>>>(xyz, nidx, W_bb1, f);
    k_stats<<<dim3(2,80),256>>>(f + F_BUFA, f, PP, 64, OBN1);
    k_finalize<<<1,64>>>(f, OBN1, 64, iPP, g_mlp1, b_mlp1);
    k_finalize<<<1,64>>>(f, OBN2, 64, iSS, g_bb1, b_bb1);
    k_finalize<<<1,256>>>(f, OBN7, 256, iPP, g_sc, b_sc);

    k_attpool1<<<444,256,20608>>>(f, xyz, nidx, W_bb1);
    k_rowsT<64><<<1280,256,51456>>>(f + F_AGG, f + F_BUFA, W_a1m);
    k_stats<<<dim3(2,80),256>>>(f + F_BUFA, f, PP, 64, OBN3);
    k_finalize<<<1,64>>>(f, OBN3, 64, iPP, g_att1, b_att1);
    k_y4stats<<<444,256,57856>>>(xyz, nidx, W_bb1, W_bb2, f);
    k_finalize<<<1,64>>>(f, OBN4, 64, iSS, g_bb2, b_bb2);

    k_attpool2<<<444,256,45440>>>(f, xyz, nidx, W_bb1, W_bb2);
    k_rowsT<128><<<1280,256,84480>>>(f + F_AGG, f + F_AGG, W_a2m);
    k_stats<<<dim3(4,80),256>>>(f + F_AGG, f, PP, 128, OBN5);
    k_finalize<<<1,128>>>(f, OBN5, 128, iPP, g_att2, b_att2);

    k_y6stats<<<296,256,84992>>>(f, W_mlp2);
    k_finalize<<<1,256>>>(f, OBN6, 256, iPP, g_mlp2, b_mlp2);

    k_zeroctr<<<1,1>>>(f);
    k_final<<<NBLK_FINAL,256,50176>>>(f, feature, W_mlp2, W_sc);
}

// round 13
// speedup vs baseline: 1.1041x; 1.1041x over previous
#include <cuda_runtime.h>
#include <mma.h>
using namespace nvcuda;

#define NN 20480
#define PP (2*NN)           // 40960 points
#define SS (PP*16)          // 655360 samples

#define OBN1 0
#define OBN2 64
#define OBN3 128
#define OBN4 192
#define OBN5 256
#define OBN6 384
#define OBN7 640

// ---- scratch layout inside d_out (floats). NO device globals anywhere. ----
#define F_BUFA  0u
#define F_SML   5201920u
#define F_WT1   (F_SML)
#define F_WT2   (F_SML+16384u)
#define F_ACC   (F_SML+32768u)
#define F_SCALE (F_SML+34816u)
#define F_SHIFT (F_SML+35840u)
#define F_FLAG  (F_SML+36864u)
#define F_AGG   5242880u

#define NBLK_FINAL 512
#define PTS_FINAL  80

// ---------- helpers ----------
__device__ __forceinline__ int ldidx(const int* __restrict__ idx, size_t s, int u64) {
    return u64 ? __ldg(&idx[2*s]) : __ldg(&idx[s]);
}

__device__ __forceinline__ void build_e(const float* __restrict__ xyz,
                                        const int* __restrict__ idx, size_t s, int u64,
                                        float* e) {
    int p = (int)(s >> 4);
    int b = p / NN, n = p % NN;
    int ni = ldidx(idx, s, u64);
    const float* cx = &xyz[((size_t)b*NN + n)*3];
    const float* nx = &xyz[((size_t)b*NN + ni)*3];
    float c0=__ldg(cx), c1=__ldg(cx+1), c2=__ldg(cx+2);
    float n0=__ldg(nx), n1=__ldg(nx+1), n2=__ldg(nx+2);
    float r0=c0-n0, r1=c1-n1, r2=c2-n2;
    e[0]=sqrtf(r0*r0+r1*r1+r2*r2);
    e[1]=r0; e[2]=r1; e[3]=r2; e[4]=c0; e[5]=c1; e[6]=c2; e[7]=n0; e[8]=n1; e[9]=n2;
}

template<int CIN>
__device__ __forceinline__ float4 dot4(const float* Wsh, int og, const float* x) {
    float4 a = make_float4(0.f,0.f,0.f,0.f);
    const float* w0 = Wsh + (4*og+0)*CIN;
    const float* w1 = Wsh + (4*og+1)*CIN;
    const float* w2 = Wsh + (4*og+2)*CIN;
    const float* w3 = Wsh + (4*og+3)*CIN;
#pragma unroll
    for (int cq = 0; cq < CIN/4; cq++) {
        float4 p0 = *(const float4*)(w0+4*cq);
        float4 p1 = *(const float4*)(w1+4*cq);
        float4 p2 = *(const float4*)(w2+4*cq);
        float4 p3 = *(const float4*)(w3+4*cq);
        float x0=x[4*cq], x1=x[4*cq+1], x2=x[4*cq+2], x3=x[4*cq+3];
        a.x += p0.x*x0+p0.y*x1+p0.z*x2+p0.w*x3;
        a.y += p1.x*x0+p1.y*x1+p1.z*x2+p1.w*x3;
        a.z += p2.x*x0+p2.y*x1+p2.z*x2+p2.w*x3;
        a.w += p3.x*x0+p3.y*x1+p3.z*x2+p3.w*x3;
    }
    return a;
}

// ---------- kernels ----------
__global__ void k_init(const int* __restrict__ idx, float* __restrict__ f) {
    __shared__ int hi[256];
    int t = threadIdx.x;
    long long v = __ldg(&((const long long*)idx)[t]);
    hi[t] = (int)((unsigned long long)v >> 32);
    __syncthreads();
    if (t == 0) {
        int o = 0;
        for (int j = 0; j < 256; j++) o |= hi[j];
        *(int*)&f[F_FLAG] = (o == 0) ? 1 : 0;
    }
    for (int i = t; i < 2048; i += 256) f[F_ACC + i] = 0.f;
}

// plain transpose: WT[c][o] = W[o][c]
__global__ void k_transpose(const float* __restrict__ W1, const float* __restrict__ W2,
                            float* __restrict__ f) {
    const float* src = blockIdx.x ? W2 : W1;
    float* dst = f + (blockIdx.x ? F_WT2 : F_WT1);
    for (int i = threadIdx.x; i < 16384; i += 256) {
        int o = i >> 7, c = i & 127;
        dst[c*128 + o] = __ldg(&src[i]);
    }
}

// mlp1 (64->64) raw -> bufA. grid 160x256.
__global__ __launch_bounds__(256) void k_mlp1(const float* __restrict__ feat,
                                              const float* __restrict__ W1,
                                              float* __restrict__ f) {
    __shared__ float Wsh[4096];
    int t = threadIdx.x;
    int p = blockIdx.x*256 + t;
    int b = p / NN, n = p % NN;
    float x[64];
#pragma unroll
    for (int c = 0; c < 64; c++) x[c] = __ldg(&feat[((size_t)(b*64+c))*NN + n]);
    for (int i = t; i < 4096; i += 256) Wsh[i] = __ldg(&W1[i]);
    __syncthreads();
#pragma unroll 2
    for (int og = 0; og < 16; og++)
        *(float4*)&f[F_BUFA + (size_t)p*64 + 4*og] = dot4<64>(Wsh, og, x);
}

// shortcut conv stats only. dyn smem 74752B.
__global__ __launch_bounds__(256) void k_scstats(const float* __restrict__ feat,
                                                 const float* __restrict__ Wsc,
                                                 float* __restrict__ f) {
    extern __shared__ float sh[];
    float* Wsh = sh;
    float* xf  = sh + 16640;
    int t = threadIdx.x;
    for (int i = t; i < 16384; i += 256) Wsh[(i>>6)*65 + (i&63)] = __ldg(&Wsc[i]);
    float sum = 0.f, sq = 0.f;
    for (int tile = blockIdx.x; tile < PP/32; tile += gridDim.x) {
        __syncthreads();
        int pbase = tile*32, b = pbase/NN, nb = pbase%NN;
        for (int i = t; i < 2048; i += 256) {
            int cin = i >> 5, ii = i & 31;
            xf[i] = __ldg(&feat[((size_t)(b*64+cin))*NN + nb + ii]);
        }
        __syncthreads();
        float a[32];
#pragma unroll
        for (int u = 0; u < 32; u++) a[u] = 0.f;
#pragma unroll 4
        for (int j = 0; j < 64; j++) {
            float w = Wsh[t*65 + j];
            const float4* xr = (const float4*)&xf[j*32];
#pragma unroll
            for (int i4 = 0; i4 < 8; i4++) {
                float4 xv = xr[i4];
                a[i4*4+0] += w*xv.x; a[i4*4+1] += w*xv.y;
                a[i4*4+2] += w*xv.z; a[i4*4+3] += w*xv.w;
            }
        }
#pragma unroll
        for (int u = 0; u < 32; u++) { sum += a[u]; sq += a[u]*a[u]; }
    }
    atomicAdd(&f[F_ACC + OBN7 + t], sum);
    atomicAdd(&f[F_ACC + 1024 + OBN7 + t], sq);
}

// bb1 stats only.
__global__ __launch_bounds__(256) void k_bn2stats(const float* __restrict__ xyz,
                                                  const int* __restrict__ idx,
                                                  const float* __restrict__ Wbb1,
                                                  float* __restrict__ f) {
    __shared__ float Wsh[704], esh[1408], red[2048];
    int t = threadIdx.x;
    int u64 = __ldg((const int*)&f[F_FLAG]);
    for (int i = t; i < 640; i += 256) Wsh[(i/10)*11 + (i%10)] = __ldg(&Wbb1[i]);
    float acc[8];
#pragma unroll
    for (int i = 0; i < 8; i++) acc[i] = 0.f;
    int q = t & 15, so = t >> 4;
    for (int tile = blockIdx.x; tile < SS/128; tile += gridDim.x) {
        __syncthreads();
        if (t < 128) build_e(xyz, idx, (size_t)tile*128 + t, u64, &esh[t*11]);
        __syncthreads();
        float a4[32];
#pragma unroll
        for (int u = 0; u < 32; u++) a4[u] = 0.f;
#pragma unroll
        for (int c = 0; c < 10; c++) {
            float w0 = Wsh[(4*q+0)*11+c], w1 = Wsh[(4*q+1)*11+c];
            float w2 = Wsh[(4*q+2)*11+c], w3 = Wsh[(4*q+3)*11+c];
#pragma unroll
            for (int j = 0; j < 8; j++) {
                float ev = esh[(j*16+so)*11+c];
                a4[j*4+0] += w0*ev; a4[j*4+1] += w1*ev;
                a4[j*4+2] += w2*ev; a4[j*4+3] += w3*ev;
            }
        }
#pragma unroll
        for (int j = 0; j < 8; j++)
#pragma unroll
            for (int cc = 0; cc < 4; cc++) {
                float v = a4[j*4+cc];
                acc[cc] += v; acc[4+cc] += v*v;
            }
    }
    __syncthreads();
#pragma unroll
    for (int i = 0; i < 8; i++) red[t*8+i] = acc[i];
    __syncthreads();
    if (t < 128) {
        int qq = t & 15, ii = t >> 4;
        float s = 0.f;
#pragma unroll
        for (int g = 0; g < 16; g++) s += red[(g*16+qq)*8+ii];
        int ch = 4*qq + (ii & 3);
        if (ii < 4) atomicAdd(&f[F_ACC + OBN2 + ch], s);
        else        atomicAdd(&f[F_ACC + 1024 + OBN2 + ch], s);
    }
}

// bb2 stats only. dyn smem 57856B.
__global__ __launch_bounds__(256) void k_y4stats(const float* __restrict__ xyz,
                                                 const int* __restrict__ idx,
                                                 const float* __restrict__ Wbb1,
                                                 const float* __restrict__ Wbb2,
                                                 float* __restrict__ f) {
    extern __shared__ float sh[];
    float* W1s  = sh;
    float* W2s  = sh + 704;
    float* y2sh = sh + 4864;
    float* esh  = sh + 13056;
    int t = threadIdx.x;
    int u64 = __ldg((const int*)&f[F_FLAG]);
    for (int i = t; i < 640; i += 256) W1s[(i/10)*11 + (i%10)] = __ldg(&Wbb1[i]);
    for (int i = t; i < 4096; i += 256) W2s[(i>>6)*65 + (i&63)] = __ldg(&Wbb2[i]);
    float acc[8];
#pragma unroll
    for (int i = 0; i < 8; i++) acc[i] = 0.f;
    int q = t & 15, so = t >> 4;
    for (int tile = blockIdx.x; tile < SS/128; tile += gridDim.x) {
        __syncthreads();
        if (t < 128) build_e(xyz, idx, (size_t)tile*128 + t, u64, &esh[t*11]);
        __syncthreads();
        {
            float a4[32];
#pragma unroll
            for (int u = 0; u < 32; u++) a4[u] = 0.f;
#pragma unroll
            for (int c = 0; c < 10; c++) {
                float w0 = W1s[(4*q+0)*11+c], w1 = W1s[(4*q+1)*11+c];
                float w2 = W1s[(4*q+2)*11+c], w3 = W1s[(4*q+3)*11+c];
#pragma unroll
                for (int j = 0; j < 8; j++) {
                    float ev = esh[(j*16+so)*11+c];
                    a4[j*4+0] += w0*ev; a4[j*4+1] += w1*ev;
                    a4[j*4+2] += w2*ev; a4[j*4+3] += w3*ev;
                }
            }
#pragma unroll
            for (int j = 0; j < 8; j++)
#pragma unroll
                for (int cc = 0; cc < 4; cc++) {
                    int ch = OBN2 + 4*q + cc;
                    y2sh[(j*16+so)*64 + 4*q + cc] =
                        fmaxf(a4[j*4+cc]*f[F_SCALE+ch]+f[F_SHIFT+ch], 0.f);
                }
        }
        __syncthreads();
        {
            float a4[32];
#pragma unroll
            for (int u = 0; u < 32; u++) a4[u] = 0.f;
#pragma unroll 4
            for (int c = 0; c < 64; c++) {
                float w0 = W2s[(4*q+0)*65+c], w1 = W2s[(4*q+1)*65+c];
                float w2 = W2s[(4*q+2)*65+c], w3 = W2s[(4*q+3)*65+c];
#pragma unroll
                for (int j = 0; j < 8; j++) {
                    float yv = y2sh[(j*16+so)*64+c];
                    a4[j*4+0] += w0*yv; a4[j*4+1] += w1*yv;
                    a4[j*4+2] += w2*yv; a4[j*4+3] += w3*yv;
                }
            }
#pragma unroll
            for (int j = 0; j < 8; j++)
#pragma unroll
                for (int cc = 0; cc < 4; cc++) {
                    float v = a4[j*4+cc];
                    acc[cc] += v; acc[4+cc] += v*v;
                }
        }
    }
    __syncthreads();
#pragma unroll
    for (int i = 0; i < 8; i++) y2sh[t*8+i] = acc[i];
    __syncthreads();
    if (t < 128) {
        int qq = t & 15, ii = t >> 4;
        float s = 0.f;
#pragma unroll
        for (int g = 0; g < 16; g++) s += y2sh[(g*16+qq)*8+ii];
        int ch = 4*qq + (ii & 3);
        if (ii < 4) atomicAdd(&f[F_ACC + OBN4 + ch], s);
        else        atomicAdd(&f[F_ACC + 1024 + OBN4 + ch], s);
    }
}

// generic column stats
__global__ void k_stats(const float* __restrict__ buf, float* __restrict__ f,
                        int nrows, int C, int off) {
    __shared__ float rs[256], rq[256];
    int t = threadIdx.x;
    int c = t & 31, r = t >> 5;
    int col = blockIdx.x*32 + c;
    float s = 0.f, q = 0.f;
    int stride = gridDim.y*8;
    for (int p = blockIdx.y*8 + r; p < nrows; p += stride) {
        float v = __ldg(&buf[(size_t)p*C + col]);
        s += v; q += v*v;
    }
    rs[t] = s; rq[t] = q;
    __syncthreads();
    if (t < 32) {
        float ss = 0.f, qq = 0.f;
#pragma unroll
        for (int j = 0; j < 8; j++) { ss += rs[j*32+t]; qq += rq[j*32+t]; }
        atomicAdd(&f[F_ACC + off + blockIdx.x*32 + t], ss);
        atomicAdd(&f[F_ACC + 1024 + off + blockIdx.x*32 + t], qq);
    }
}

__global__ void k_finalize(float* __restrict__ f, int off, int C, float invn,
                           const float* __restrict__ gamma, const float* __restrict__ beta) {
    int c = threadIdx.x;
    if (c < C) {
        float mean = f[F_ACC+off+c]*invn;
        float var  = f[F_ACC+1024+off+c]*invn - mean*mean;
        float sc   = __ldg(&gamma[c]) * rsqrtf(var + 1e-5f);
        f[F_SCALE+off+c] = sc;
        f[F_SHIFT+off+c] = __ldg(&beta[c]) - mean*sc;
    }
}

// wmma tf32 score GEMM: per warp, one point-half, 32 output channels (2 n-tiles).
// scores[k][o] = sum_c fsh[k][c] * WT[c][o]
__device__ __forceinline__ void att_score_mma(const float* __restrict__ fsh,
                                              float* __restrict__ ssh,
                                              const float* __restrict__ WT,
                                              int warp) {
    int half = warp >> 2;
    int o0 = (warp & 3) * 32;
    const float* A = fsh + half*2048;
    float* S = ssh + half*2048;
    wmma::fragment<wmma::accumulator,16,16,8,float> c0, c1;
    wmma::fill_fragment(c0, 0.f);
    wmma::fill_fragment(c1, 0.f);
#pragma unroll
    for (int k0 = 0; k0 < 128; k0 += 8) {
        wmma::fragment<wmma::matrix_a,16,16,8,wmma::precision::tf32,wmma::row_major> a;
        wmma::load_matrix_sync(a, A + k0, 128);
#pragma unroll
        for (int i = 0; i < a.num_elements; i++) a.x[i] = wmma::__float_to_tf32(a.x[i]);
        wmma::fragment<wmma::matrix_b,16,16,8,wmma::precision::tf32,wmma::row_major> b0, b1;
        wmma::load_matrix_sync(b0, WT + k0*128 + o0, 128);
        wmma::load_matrix_sync(b1, WT + k0*128 + o0 + 16, 128);
#pragma unroll
        for (int i = 0; i < b0.num_elements; i++) {
            b0.x[i] = wmma::__float_to_tf32(b0.x[i]);
            b1.x[i] = wmma::__float_to_tf32(b1.x[i]);
        }
        wmma::mma_sync(c0, a, b0, c0);
        wmma::mma_sync(c1, a, b1, c1);
    }
    wmma::store_matrix_sync(S + o0, c0, 128, wmma::mem_row_major);
    wmma::store_matrix_sync(S + o0 + 16, c1, 128, wmma::mem_row_major);
}

// softmax + weighted aggregation from precomputed scores
__device__ __forceinline__ void att_epilogue(const float* __restrict__ fsh,
                                             const float* __restrict__ ssh,
                                             float* __restrict__ f,
                                             int pair, int half, int o) {
    const float* ff = fsh + half*2048;
    const float* S  = ssh + half*2048;
    float acc[16];
#pragma unroll
    for (int k = 0; k < 16; k++) acc[k] = S[k*128 + o];
    float m = acc[0];
#pragma unroll
    for (int k = 1; k < 16; k++) m = fmaxf(m, acc[k]);
    float den = 0.f;
#pragma unroll
    for (int k = 0; k < 16; k++) { acc[k] = __expf(acc[k]-m); den += acc[k]; }
    float a = 0.f;
#pragma unroll
    for (int k = 0; k < 16; k++) a += ff[k*128+o]*acc[k];
    f[F_AGG + ((size_t)pair*2 + half)*128 + o] = a / den;
}

// prefetch next pair: gather rows (2x float4) + e-inputs (t<32: 6 floats)
__device__ __forceinline__ void att_prefetch(const float* __restrict__ f,
                                             const float* __restrict__ xyz,
                                             const int* __restrict__ idx,
                                             int pair, int t, int u64, int q4,
                                             float4* gv, float* er) {
    if (pair >= PP/2) return;
    int k = t >> 4;
#pragma unroll
    for (int ph = 0; ph < 2; ph++) {
        int p = pair*2 + ph;
        size_t s = (size_t)p*16 + k;
        int ni = ldidx(idx, s, u64);
        size_t pn = (size_t)(p / NN) * NN + ni;
        gv[ph] = __ldg((const float4*)&f[F_BUFA + pn*64 + q4]);
    }
    if (t < 32) {
        size_t se = (size_t)pair*32 + t;
        int pe = pair*2 + (t >> 4);
        int be = pe / NN, ne = pe % NN;
        int nie = ldidx(idx, se, u64);
        const float* cx = &xyz[((size_t)be*NN + ne)*3];
        const float* nx = &xyz[((size_t)be*NN + nie)*3];
        er[0]=__ldg(cx);  er[1]=__ldg(cx+1); er[2]=__ldg(cx+2);
        er[3]=__ldg(nx);  er[4]=__ldg(nx+1); er[5]=__ldg(nx+2);
    }
}

__device__ __forceinline__ void commit_e(float* __restrict__ esh, const float* er, int t) {
    if (t < 32) {
        float r0 = er[0]-er[3], r1 = er[1]-er[4], r2 = er[2]-er[5];
        float* e = &esh[t*11];
        e[0] = sqrtf(r0*r0 + r1*r1 + r2*r2);
        e[1]=r0; e[2]=r1; e[3]=r2;
        e[4]=er[0]; e[5]=er[1]; e[6]=er[2]; e[7]=er[3]; e[8]=er[4]; e[9]=er[5];
    }
}

// att-pool 1: staging + wmma scores + scalar epilogue. dyn smem 36992B.
__global__ __launch_bounds__(256) void k_attpool1(float* __restrict__ f,
                                                  const float* __restrict__ xyz,
                                                  const int* __restrict__ idx,
                                                  const float* __restrict__ Wbb1) {
    extern __shared__ float sh[];
    float* fsh = sh;           // 4096
    float* ssh = sh + 4096;    // 4096
    float* W1s = sh + 8192;    // 704
    float* esh = sh + 8896;    // 352
    const float* WT = f + F_WT1;
    int t = threadIdx.x;
    int u64 = __ldg((const int*)&f[F_FLAG]);
    for (int i = t; i < 640; i += 256) W1s[(i/10)*11 + (i%10)] = __ldg(&Wbb1[i]);
    int half = t >> 7, o = t & 127;
    int kq = t >> 4, q4 = (t & 15)*4, qq = t & 15;
    int warp = t >> 5;
    float s1[4], h1[4], s2[4], h2[4];
#pragma unroll
    for (int c = 0; c < 4; c++) {
        s1[c] = __ldg(&f[F_SCALE+OBN1+q4+c]); h1[c] = __ldg(&f[F_SHIFT+OBN1+q4+c]);
        s2[c] = __ldg(&f[F_SCALE+OBN2+q4+c]); h2[c] = __ldg(&f[F_SHIFT+OBN2+q4+c]);
    }
    float4 gv[2]; float er[6];
    int step = gridDim.x;
    att_prefetch(f, xyz, idx, blockIdx.x, t, u64, q4, gv, er);

    for (int pair = blockIdx.x; pair < PP/2; pair += step) {
        commit_e(esh, er, t);
#pragma unroll
        for (int ph = 0; ph < 2; ph++) {
            float4 v = gv[ph];
            v.x = fmaxf(v.x*s1[0]+h1[0],0.f); v.y = fmaxf(v.y*s1[1]+h1[1],0.f);
            v.z = fmaxf(v.z*s1[2]+h1[2],0.f); v.w = fmaxf(v.w*s1[3]+h1[3],0.f);
            *(float4*)&fsh[ph*2048 + kq*128 + q4] = v;
        }
        __syncthreads();
#pragma unroll
        for (int ph = 0; ph < 2; ph++) {
            const float* e = &esh[(ph*16 + kq)*11];
            float a0=0,a1=0,a2=0,a3=0;
#pragma unroll
            for (int c = 0; c < 10; c++) {
                float ev = e[c];
                a0 += W1s[(4*qq+0)*11+c]*ev; a1 += W1s[(4*qq+1)*11+c]*ev;
                a2 += W1s[(4*qq+2)*11+c]*ev; a3 += W1s[(4*qq+3)*11+c]*ev;
            }
            float4 v;
            v.x = fmaxf(a0*s2[0]+h2[0],0.f); v.y = fmaxf(a1*s2[1]+h2[1],0.f);
            v.z = fmaxf(a2*s2[2]+h2[2],0.f); v.w = fmaxf(a3*s2[3]+h2[3],0.f);
            *(float4*)&fsh[ph*2048 + kq*128 + 64 + q4] = v;
        }
        __syncthreads();
        att_prefetch(f, xyz, idx, pair + step, t, u64, q4, gv, er);
        att_score_mma(fsh, ssh, WT, warp);
        __syncthreads();
        att_epilogue(fsh, ssh, f, pair, half, o);
        __syncthreads();
    }
}

// att-pool 2. dyn smem 61824B.
__global__ __launch_bounds__(256) void k_attpool2(float* __restrict__ f,
                                                  const float* __restrict__ xyz,
                                                  const int* __restrict__ idx,
                                                  const float* __restrict__ Wbb1,
                                                  const float* __restrict__ Wbb2) {
    extern __shared__ float sh[];
    float* fsh = sh;           // 4096
    float* ssh = sh + 4096;    // 4096
    float* W1s = sh + 8192;    // 704
    float* W2s = sh + 8896;    // 4160
    float* esh = sh + 13056;   // 352
    float* y2t = sh + 13408;   // 2048
    const float* WT = f + F_WT2;
    int t = threadIdx.x;
    int u64 = __ldg((const int*)&f[F_FLAG]);
    for (int i = t; i < 640; i += 256) W1s[(i/10)*11 + (i%10)] = __ldg(&Wbb1[i]);
    for (int i = t; i < 4096; i += 256) W2s[(i>>6)*65 + (i&63)] = __ldg(&Wbb2[i]);
    int half = t >> 7, o = t & 127;
    int kq = t >> 4, q4 = (t & 15)*4, qq = t & 15;
    int warp = t >> 5;
    float s3[4], h3[4], s2[4], h2[4], s4[4], h4[4];
#pragma unroll
    for (int c = 0; c < 4; c++) {
        s3[c] = __ldg(&f[F_SCALE+OBN3+q4+c]); h3[c] = __ldg(&f[F_SHIFT+OBN3+q4+c]);
        s2[c] = __ldg(&f[F_SCALE+OBN2+q4+c]); h2[c] = __ldg(&f[F_SHIFT+OBN2+q4+c]);
        s4[c] = __ldg(&f[F_SCALE+OBN4+q4+c]); h4[c] = __ldg(&f[F_SHIFT+OBN4+q4+c]);
    }
    float4 gv[2]; float er[6];
    int step = gridDim.x;
    att_prefetch(f, xyz, idx, blockIdx.x, t, u64, q4, gv, er);

    for (int pair = blockIdx.x; pair < PP/2; pair += step) {
        commit_e(esh, er, t);
#pragma unroll
        for (int ph = 0; ph < 2; ph++) {
            float4 v = gv[ph];
            v.x = fmaxf(v.x*s3[0]+h3[0],0.f); v.y = fmaxf(v.y*s3[1]+h3[1],0.f);
            v.z = fmaxf(v.z*s3[2]+h3[2],0.f); v.w = fmaxf(v.w*s3[3]+h3[3],0.f);
            *(float4*)&fsh[ph*2048 + kq*128 + q4] = v;
        }
        __syncthreads();
#pragma unroll
        for (int ph = 0; ph < 2; ph++) {
            int sl = ph*16 + kq;
            const float* e = &esh[sl*11];
            float a0=0,a1=0,a2=0,a3=0;
#pragma unroll
            for (int c = 0; c < 10; c++) {
                float ev = e[c];
                a0 += W1s[(4*qq+0)*11+c]*ev; a1 += W1s[(4*qq+1)*11+c]*ev;
                a2 += W1s[(4*qq+2)*11+c]*ev; a3 += W1s[(4*qq+3)*11+c]*ev;
            }
            float4 v;
            v.x = fmaxf(a0*s2[0]+h2[0],0.f); v.y = fmaxf(a1*s2[1]+h2[1],0.f);
            v.z = fmaxf(a2*s2[2]+h2[2],0.f); v.w = fmaxf(a3*s2[3]+h2[3],0.f);
            *(float4*)&y2t[sl*64 + q4] = v;
        }
        __syncthreads();
#pragma unroll
        for (int ph = 0; ph < 2; ph++) {
            int sl = ph*16 + kq;
            const float* y2 = &y2t[sl*64];
            float a0=0,a1=0,a2=0,a3=0;
#pragma unroll 4
            for (int c = 0; c < 64; c++) {
                float yv = y2[c];
                a0 += W2s[(4*qq+0)*65+c]*yv; a1 += W2s[(4*qq+1)*65+c]*yv;
                a2 += W2s[(4*qq+2)*65+c]*yv; a3 += W2s[(4*qq+3)*65+c]*yv;
            }
            float4 v;
            v.x = fmaxf(a0*s4[0]+h4[0],0.f); v.y = fmaxf(a1*s4[1]+h4[1],0.f);
            v.z = fmaxf(a2*s4[2]+h4[2],0.f); v.w = fmaxf(a3*s4[3]+h4[3],0.f);
            *(float4*)&fsh[ph*2048 + kq*128 + 64 + q4] = v;
        }
        __syncthreads();
        att_prefetch(f, xyz, idx, pair + step, t, u64, q4, gv, er);
        att_score_mma(fsh, ssh, WT, warp);
        __syncthreads();
        att_epilogue(fsh, ssh, f, pair, half, o);
        __syncthreads();
    }
}

// tiled rows GEMM.
template<int O>
__global__ __launch_bounds__(256) void k_rowsT(const float* __restrict__ X,
                                               float* __restrict__ Y,
                                               const float* __restrict__ W) {
    extern __shared__ float sh[];
    float* Wsh = sh;
    float* xsh = sh + O*129;
    constexpr int NP = (O == 64) ? 8 : 16;
    int t = threadIdx.x;
    int o = t & (O-1), h = t / O;
    for (int i = t; i < O*128; i += 256) Wsh[(i>>7)*129 + (i&127)] = __ldg(&W[i]);
    for (int tile = blockIdx.x; tile < PP/32; tile += gridDim.x) {
        __syncthreads();
        for (int i = t; i < 4096; i += 256) {
            int pt = i >> 7, ch = i & 127;
            xsh[ch*36 + pt] = __ldg(&X[((size_t)tile*32 + pt)*128 + ch]);
        }
        __syncthreads();
        float acc[NP];
#pragma unroll
        for (int i = 0; i < NP; i++) acc[i] = 0.f;
#pragma unroll 4
        for (int j = 0; j < 128; j++) {
            float w = Wsh[o*129 + j];
            const float4* xr = (const float4*)&xsh[j*36 + h*NP];
#pragma unroll
            for (int i4 = 0; i4 < NP/4; i4++) {
                float4 xv = xr[i4];
                acc[i4*4+0] += w*xv.x; acc[i4*4+1] += w*xv.y;
                acc[i4*4+2] += w*xv.z; acc[i4*4+3] += w*xv.w;
            }
        }
#pragma unroll
        for (int i = 0; i < NP; i++)
            Y[((size_t)tile*32 + h*NP + i)*O + o] = acc[i];
    }
}

// mlp2 stats only. dyn smem 84992B.
__global__ __launch_bounds__(256) void k_y6stats(float* __restrict__ f,
                                                 const float* __restrict__ Wm) {
    extern __shared__ float sh[];
    float* Wsh = sh;
    float* xsh = sh + 16640;
    int t = threadIdx.x;
    float sum = 0.f, sq = 0.f;
    for (int tile = blockIdx.x; tile < PP/32; tile += gridDim.x) {
        __syncthreads();
        for (int i = t; i < 4096; i += 256) {
            int pt = i >> 7, ch = i & 127;
            float v = __ldg(&f[F_AGG + ((size_t)tile*32 + pt)*128 + ch]);
            xsh[ch*36 + pt] = fmaxf(v*f[F_SCALE+OBN5+ch]+f[F_SHIFT+OBN5+ch], 0.f);
        }
        float a[32];
#pragma unroll
        for (int u = 0; u < 32; u++) a[u] = 0.f;
        for (int chunk = 0; chunk < 2; chunk++) {
            __syncthreads();
            for (int i = t; i < 16384; i += 256)
                Wsh[(i>>6)*65 + (i&63)] = __ldg(&Wm[(i>>6)*128 + chunk*64 + (i&63)]);
            __syncthreads();
#pragma unroll 4
            for (int j = 0; j < 64; j++) {
                float w = Wsh[t*65 + j];
                const float4* xr = (const float4*)&xsh[(chunk*64+j)*36];
#pragma unroll
                for (int i4 = 0; i4 < 8; i4++) {
                    float4 xv = xr[i4];
                    a[i4*4+0] += w*xv.x; a[i4*4+1] += w*xv.y;
                    a[i4*4+2] += w*xv.z; a[i4*4+3] += w*xv.w;
                }
            }
        }
#pragma unroll
        for (int u = 0; u < 32; u++) { sum += a[u]; sq += a[u]*a[u]; }
    }
    atomicAdd(&f[F_ACC + OBN6 + t], sum);
    atomicAdd(&f[F_ACC + 1024 + OBN6 + t], sq);
}

__global__ void k_zeroctr(float* __restrict__ f) {
    ((int*)f)[0] = 0;
    ((int*)f)[1] = 0;
}

// FINAL: grid-barrier kernel. dyn smem 50176B.
__global__ __launch_bounds__(256, 4) void k_final(float* __restrict__ f,
                                                  const float* __restrict__ feat,
                                                  const float* __restrict__ Wm,
                                                  const float* __restrict__ Wsc) {
    extern __shared__ float sh[];
    float* h     = sh;
    float* featT = sh + 10240;
    float* sml   = sh + 11264;
    int t = threadIdx.x;
    int pb = blockIdx.x * PTS_FINAL;
    int b = (pb >= NN) ? 1 : 0;
    int n0b = pb - b*NN;
    int* ctr  = (int*)&f[0];
    int* ctr2 = (int*)&f[1];

    for (int i = t; i < 1280; i += 256) {
        unsigned src;
        if (i < 128)       src = F_SCALE + OBN5 + i;
        else if (i < 256)  src = F_SHIFT + OBN5 + (i-128);
        else if (i < 512)  src = F_SCALE + OBN6 + (i-256);
        else if (i < 768)  src = F_SHIFT + OBN6 + (i-512);
        else if (i < 1024) src = F_SCALE + OBN7 + (i-768);
        else               src = F_SHIFT + OBN7 + (i-1024);
        sml[i] = __ldg(&f[src]);
    }
    for (int i = t; i < PTS_FINAL*128; i += 256) {
        int pt = i >> 7, ch = i & 127;
        float v = __ldg(&f[F_AGG + ((size_t)(pb + pt))*128 + ch]);
        h[i] = fmaxf(v*__ldg(&f[F_SCALE+OBN5+ch]) + __ldg(&f[F_SHIFT+OBN5+ch]), 0.f);
    }
    __syncthreads();

    if (t == 0) {
        __threadfence();
        atomicAdd(ctr, 1);
        while (atomicAdd(ctr, 0) < NBLK_FINAL) { }
        __threadfence();
    }
    __syncthreads();

    int c = t;
    float s6 = sml[256 + c], h6 = sml[512 + c];
    float s7 = sml[768 + c], h7 = sml[1024 + c];
    float sv0 = 0.f, sv1 = 0.f;
    bool owner = (pb == 0) && (c == 0);

    for (int tt = 0; tt < PTS_FINAL/16; tt++) {
        __syncthreads();
        int n0 = n0b + tt*16;
        for (int i = t; i < 1024; i += 256) {
            int cin = i >> 4, ii = i & 15;
            featT[cin*16 + ii] = __ldg(&feat[((size_t)(b*64+cin))*NN + n0 + ii]);
        }
        __syncthreads();

        float acc[16];
#pragma unroll
        for (int i = 0; i < 16; i++) acc[i] = 0.f;
        const float4* wrow = (const float4*)(Wm + (size_t)c*128);
        const float* hb = h + (tt*16)*128;
#pragma unroll 4
        for (int kk = 0; kk < 32; kk++) {
            float4 w = __ldg(&wrow[kk]);
#pragma unroll
            for (int i = 0; i < 16; i++) {
                float4 hv = *(const float4*)&hb[i*128 + kk*4];
                acc[i] += w.x*hv.x + w.y*hv.y + w.z*hv.z + w.w*hv.w;
            }
        }
#pragma unroll
        for (int i = 0; i < 16; i++) acc[i] = acc[i]*s6 + h6 + h7;

        const float4* srow = (const float4*)(Wsc + (size_t)c*64);
#pragma unroll 4
        for (int j4 = 0; j4 < 16; j4++) {
            float4 w = __ldg(&srow[j4]);
            float wx = w.x*s7, wy = w.y*s7, wz = w.z*s7, ww = w.w*s7;
            const float* f0 = &featT[(j4*4+0)*16];
            const float* f1 = &featT[(j4*4+1)*16];
            const float* f2 = &featT[(j4*4+2)*16];
            const float* f3 = &featT[(j4*4+3)*16];
#pragma unroll
            for (int i = 0; i < 16; i++)
                acc[i] += wx*f0[i] + wy*f1[i] + wz*f2[i] + ww*f3[i];
        }
        size_t obase = ((size_t)(b*256 + c))*NN + n0;
#pragma unroll
        for (int i = 0; i < 16; i++) {
            float v = acc[i];
            v = (v > 0.f) ? v : 0.2f*v;
            if (owner && tt == 0 && i < 2) { if (i == 0) sv0 = v; else sv1 = v; }
            else f[obase + i] = v;
        }
    }

    __syncthreads();
    if (t == 0) {
        __threadfence();
        atomicAdd(ctr2, 1);
        if (pb == 0) {
            while (atomicAdd(ctr2, 0) < NBLK_FINAL) { }
            f[0] = sv0;
            f[1] = sv1;
        }
    }
}

// ---------- launch ----------
extern "C" void kernel_launch(void* const* d_in, const int* in_sizes, int n_in,
                              void* d_out, int out_size) {
    const float* feature = (const float*)d_in[0];
    const float* xyz     = (const float*)d_in[1];
    const int*   nidx    = (const int*)  d_in[2];
    const float* W_mlp1  = (const float*)d_in[3];
    const float* g_mlp1  = (const float*)d_in[4];
    const float* b_mlp1  = (const float*)d_in[5];
    const float* W_bb1   = (const float*)d_in[6];
    const float* g_bb1   = (const float*)d_in[7];
    const float* b_bb1   = (const float*)d_in[8];
    const float* W_a1fc  = (const float*)d_in[9];
    const float* W_a1m   = (const float*)d_in[10];
    const float* g_att1  = (const float*)d_in[11];
    const float* b_att1  = (const float*)d_in[12];
    const float* W_bb2   = (const float*)d_in[13];
    const float* g_bb2   = (const float*)d_in[14];
    const float* b_bb2   = (const float*)d_in[15];
    const float* W_a2fc  = (const float*)d_in[16];
    const float* W_a2m   = (const float*)d_in[17];
    const float* g_att2  = (const float*)d_in[18];
    const float* b_att2  = (const float*)d_in[19];
    const float* W_mlp2  = (const float*)d_in[20];
    const float* g_mlp2  = (const float*)d_in[21];
    const float* b_mlp2  = (const float*)d_in[22];
    const float* W_sc    = (const float*)d_in[23];
    const float* g_sc    = (const float*)d_in[24];
    const float* b_sc    = (const float*)d_in[25];
    float* f = (float*)d_out;

    cudaFuncSetAttribute(k_scstats,   cudaFuncAttributeMaxDynamicSharedMemorySize, 74752);
    cudaFuncSetAttribute(k_y4stats,   cudaFuncAttributeMaxDynamicSharedMemorySize, 57856);
    cudaFuncSetAttribute(k_attpool1,  cudaFuncAttributeMaxDynamicSharedMemorySize, 36992);
    cudaFuncSetAttribute(k_attpool2,  cudaFuncAttributeMaxDynamicSharedMemorySize, 61824);
    cudaFuncSetAttribute(k_y6stats,   cudaFuncAttributeMaxDynamicSharedMemorySize, 84992);
    cudaFuncSetAttribute(k_rowsT<64>, cudaFuncAttributeMaxDynamicSharedMemorySize, 51456);
    cudaFuncSetAttribute(k_rowsT<128>,cudaFuncAttributeMaxDynamicSharedMemorySize, 84480);
    cudaFuncSetAttribute(k_final,     cudaFuncAttributeMaxDynamicSharedMemorySize, 50176);

    const float iPP = 1.f/(float)PP, iSS = 1.f/(float)SS;

    k_init<<<1,256>>>(nidx, f);
    k_transpose<<<2,256>>>(W_a1fc, W_a2fc, f);
    k_mlp1<<<PP/256,256>>>(feature, W_mlp1, f);
    k_scstats<<<320,256,74752>>>(feature, W_sc, f);
    k_bn2stats<<<1184,256>>>(xyz, nidx, W_bb1, f);
    k_stats<<<dim3(2,80),256>>>(f + F_BUFA, f, PP, 64, OBN1);
    k_finalize<<<1,64>>>(f, OBN1, 64, iPP, g_mlp1, b_mlp1);
    k_finalize<<<1,64>>>(f, OBN2, 64, iSS, g_bb1, b_bb1);
    k_finalize<<<1,256>>>(f, OBN7, 256, iPP, g_sc, b_sc);

    k_attpool1<<<444,256,36992>>>(f, xyz, nidx, W_bb1);
    k_rowsT<64><<<1280,256,51456>>>(f + F_AGG, f + F_BUFA, W_a1m);
    k_stats<<<dim3(2,80),256>>>(f + F_BUFA, f, PP, 64, OBN3);
    k_finalize<<<1,64>>>(f, OBN3, 64, iPP, g_att1, b_att1);
    k_y4stats<<<444,256,57856>>>(xyz, nidx, W_bb1, W_bb2, f);
    k_finalize<<<1,64>>>(f, OBN4, 64, iSS, g_bb2, b_bb2);

    k_attpool2<<<444,256,61824>>>(f, xyz, nidx, W_bb1, W_bb2);
    k_rowsT<128><<<1280,256,84480>>>(f + F_AGG, f + F_AGG, W_a2m);
    k_stats<<<dim3(4,80),256>>>(f + F_AGG, f, PP, 128, OBN5);
    k_finalize<<<1,128>>>(f, OBN5, 128, iPP, g_att2, b_att2);

    k_y6stats<<<296,256,84992>>>(f, W_mlp2);
    k_finalize<<<1,256>>>(f, OBN6, 256, iPP, g_mlp2, b_mlp2);

    k_zeroctr<<<1,1>>>(f);
    k_final<<<NBLK_FINAL,256,50176>>>(f, feature, W_mlp2, W_sc);
}